// round 15
// baseline (speedup 1.0000x reference)
#include <cuda_runtime.h>
#include <cuda_bf16.h>
#include <mma.h>
#include <cstdint>

using namespace nvcuda;

#define BB 256
#define DD 5120
#define NN 16
#define RR 160
#define JJ 192          // RR + 32 (B/C projections)
#define KSPLIT 80
#define KCH 64          // DD / KSPLIT

// Scratch (device globals — no allocations allowed)
__device__ float g_P[KSPLIT * BB * JJ];   // split-K partials (15.7 MB)
__device__ float g_T[BB * JJ];            // reduced projections (fp32)
__device__ float g_DT[BB * DD];           // dt (5.2 MB)
__device__ __nv_bfloat16 g_WBH[DD * JJ];  // [k][j] W=[Wx|Wbc] bf16 hi
__device__ __nv_bfloat16 g_WBL[DD * JJ];  // lo
__device__ __nv_bfloat16 g_WDH[RR * DD];  // [r][d] W_dt bf16 hi
__device__ __nv_bfloat16 g_WDL[RR * DD];  // lo
__device__ __nv_bfloat16 g_TH[BB * RR];   // t bf16 hi
__device__ __nv_bfloat16 g_TL[BB * RR];   // lo

__device__ __forceinline__ float ex2f(float v) {
    float r;
    asm("ex2.approx.ftz.f32 %0, %1;" : "=f"(r) : "f"(v));
    return r;
}

typedef unsigned long long ull;

// Packed hi/lo bf16 split of a float4
__device__ __forceinline__ void cvt_hilo4(float4 f, ull& hi, ull& lo) {
    union { ull u; __nv_bfloat162 h2[2]; } H, L;
    H.h2[0] = __float22bfloat162_rn(make_float2(f.x, f.y));
    H.h2[1] = __float22bfloat162_rn(make_float2(f.z, f.w));
    float2 g01 = __bfloat1622float2(H.h2[0]);
    float2 g23 = __bfloat1622float2(H.h2[1]);
    L.h2[0] = __float22bfloat162_rn(make_float2(f.x - g01.x, f.y - g01.y));
    L.h2[1] = __float22bfloat162_rn(make_float2(f.z - g23.x, f.w - g23.y));
    hi = H.u; lo = L.u;
}

// ---------------------------------------------------------------------------
// Kernel 0 (prep): one-time fp32 -> bf16 hi/lo conversion of all weights.
// WB: [5120 k][192 j] (Wx cols 0..159, Wbc cols 160..191)  -> g_WBH/g_WBL
// WD: [160 r][5120 d]                                       -> g_WDH/g_WDL
// Also fires the h0 L2 prefetch. Grid 440 x 256, 4 float4/thread.
// ---------------------------------------------------------------------------
__global__ __launch_bounds__(256) void mamba_prep(
    const float* __restrict__ Wx, const float* __restrict__ Wbc,
    const float* __restrict__ Wdt, const float* __restrict__ h0)
{
    const int tid = threadIdx.x;
#pragma unroll
    for (int i = 0; i < 4; i++) {
        const int idx = blockIdx.x * 1024 + i * 256 + tid;
        if (idx < 245760) {                       // WB: 5120*48 float4
            const int k = idx / 48, j4 = (idx % 48) * 4;
            float4 wv;
            if (j4 < RR) wv = *(const float4*)&Wx[(size_t)k * RR + j4];
            else         wv = *(const float4*)&Wbc[(size_t)k * 32 + (j4 - RR)];
            ull hi, lo;
            cvt_hilo4(wv, hi, lo);
            *(ull*)(g_WBH + (size_t)k * JJ + j4) = hi;
            *(ull*)(g_WBL + (size_t)k * JJ + j4) = lo;
        } else {                                  // WD: 160*1280 float4
            const int id2 = idx - 245760;
            const int r = id2 / 1280, d4 = (id2 % 1280) * 4;
            float4 wv = *(const float4*)&Wdt[(size_t)r * DD + d4];
            ull hi, lo;
            cvt_hilo4(wv, hi, lo);
            *(ull*)(g_WDH + (size_t)r * DD + d4) = hi;
            *(ull*)(g_WDL + (size_t)r * DD + d4) = lo;
        }
    }
    // h0 L2 prefetch: 655360 lines over 440 blocks (1490/block, 6/thread)
    {
        const size_t total = (size_t)BB * DD * NN;
        size_t base = (size_t)blockIdx.x * 1490 * 32;
#pragma unroll
        for (int i = 0; i < 6; i++) {
            const int li = tid + i * 256;
            size_t off = base + (size_t)li * 32;
            if (li < 1490 && off < total)
                asm volatile("prefetch.global.L2 [%0];" :: "l"(h0 + off) : "memory");
        }
    }
}

// ---------------------------------------------------------------------------
// Kernel 1 (wmma): split-K GEMM via HMMA. B-operand is PRE-CONVERTED bf16 —
// loaders are pure LDG.128->STS.128 copies.
// P[ks] = x[:, ks*64 .. +64] @ W,  Grid (8, 80) = 640 CTAs, 256 threads.
// Warp w: mrow = w&1 (m = mrow*16), nq = w>>1 (n = nq*48, 3 frags).
// ---------------------------------------------------------------------------
#define PJ_AH 0
#define PJ_AL 4608            // [32][72] bf16 = 4608 B each
#define PJ_BH 9216            // [64][200] bf16 = 25600 B each
#define PJ_BL 34816
#define PJ_SMEM 60416

__global__ __launch_bounds__(256) void mamba_proj_wmma(
    const float* __restrict__ x)
{
    extern __shared__ __align__(128) char smem[];
    __nv_bfloat16* Ah = (__nv_bfloat16*)(smem + PJ_AH);
    __nv_bfloat16* Al = (__nv_bfloat16*)(smem + PJ_AL);
    __nv_bfloat16* Bh = (__nv_bfloat16*)(smem + PJ_BH);
    __nv_bfloat16* Bl = (__nv_bfloat16*)(smem + PJ_BL);
    const int tid = threadIdx.x;
    const int m0 = blockIdx.x * 32;
    const int ks = blockIdx.y;
    const int k0 = ks * KCH;

    // A: x[m0+m][k0+k] -> bf16 hi/lo (converted once per element chip-wide)
#pragma unroll
    for (int v = tid; v < 512; v += 256) {
        const int m = v >> 4, k4 = (v & 15) << 2;
        float4 xv = *(const float4*)&x[(size_t)(m0 + m) * DD + k0 + k4];
        ull hi, lo;
        cvt_hilo4(xv, hi, lo);
        *(ull*)(Ah + m * 72 + k4) = hi;
        *(ull*)(Al + m * 72 + k4) = lo;
    }
    // B: pure copy of pre-converted bf16 rows [64 k][192 j] -> ldm 200
#pragma unroll
    for (int v = tid; v < 1536; v += 256) {
        const int k = v / 24, j8 = (v % 24) * 8;
        *(float4*)(Bh + k * 200 + j8) =
            *(const float4*)(g_WBH + (size_t)(k0 + k) * JJ + j8);
        *(float4*)(Bl + k * 200 + j8) =
            *(const float4*)(g_WBL + (size_t)(k0 + k) * JJ + j8);
    }
    __syncthreads();

    const int w = tid >> 5;
    const int mrow = w & 1;       // m = mrow*16
    const int nq = w >> 1;        // n base = nq*48

    wmma::fragment<wmma::accumulator, 16, 16, 16, float> acc[3];
#pragma unroll
    for (int j = 0; j < 3; j++) wmma::fill_fragment(acc[j], 0.0f);

#pragma unroll
    for (int kc = 0; kc < 4; kc++) {
        wmma::fragment<wmma::matrix_a, 16, 16, 16, __nv_bfloat16, wmma::row_major> a_h, a_l;
        wmma::load_matrix_sync(a_h, Ah + mrow * 16 * 72 + kc * 16, 72);
        wmma::load_matrix_sync(a_l, Al + mrow * 16 * 72 + kc * 16, 72);
#pragma unroll
        for (int j = 0; j < 3; j++) {
            const int n = nq * 48 + j * 16;
            wmma::fragment<wmma::matrix_b, 16, 16, 16, __nv_bfloat16, wmma::row_major> b_h, b_l;
            wmma::load_matrix_sync(b_h, Bh + kc * 16 * 200 + n, 200);
            wmma::load_matrix_sync(b_l, Bl + kc * 16 * 200 + n, 200);
            wmma::mma_sync(acc[j], a_h, b_h, acc[j]);
            wmma::mma_sync(acc[j], a_h, b_l, acc[j]);
            wmma::mma_sync(acc[j], a_l, b_h, acc[j]);
        }
    }

    float* dst = &g_P[(size_t)ks * (BB * JJ) + (size_t)(m0 + mrow * 16) * JJ + nq * 48];
#pragma unroll
    for (int j = 0; j < 3; j++)
        wmma::store_matrix_sync(dst + j * 16, acc[j], JJ, wmma::mem_row_major);
}

// ---------------------------------------------------------------------------
// Kernel 1r: reduce split-K partials -> g_T (fp32) AND g_TH/g_TL (bf16 hi/lo
// of the first 160 cols, pre-converted for the dt GEMM). Grid 192.
// ---------------------------------------------------------------------------
__global__ __launch_bounds__(256) void mamba_reduce_kernel()
{
    const int idx = blockIdx.x * 256 + threadIdx.x;
    float s = 0.f;
#pragma unroll
    for (int ks = 0; ks < KSPLIT; ks++) s += g_P[ks * (BB * JJ) + idx];
    g_T[idx] = s;
    const int b = idx / JJ, j = idx - b * JJ;
    if (j < RR) {
        __nv_bfloat16 h = __float2bfloat16(s);
        g_TH[b * RR + j] = h;
        g_TL[b * RR + j] = __float2bfloat16(s - __bfloat162float(h));
    }
}

// ---------------------------------------------------------------------------
// Kernel 2a (wmma): dt GEMM. All operands PRE-CONVERTED -> pure-copy loaders.
// z = t @ W_dt + b_dt ; dt = softplus(z) -> g_DT
// CTA 32(b) x 64(d), K=160 in 5 chunks of 32. Grid (80, 8) = 640 CTAs.
// Warp w: mrow = w&1, nq = w>>1 (1 acc frag).
// ---------------------------------------------------------------------------
#define DT_AH 0                 // [32][160] bf16 = 10240 B each
#define DT_AL 10240
#define DT_BH 20480             // [32][72] bf16 = 4608 B each
#define DT_BL 25088
#define DT_SMEM 29696           // staging [32][64] f32 = 8192 reuses A region

__global__ __launch_bounds__(256) void mamba_dt_wmma(
    const float* __restrict__ bdt)
{
    extern __shared__ __align__(128) char smem[];
    __nv_bfloat16* Ah = (__nv_bfloat16*)(smem + DT_AH);
    __nv_bfloat16* Al = (__nv_bfloat16*)(smem + DT_AL);
    __nv_bfloat16* Bh = (__nv_bfloat16*)(smem + DT_BH);
    __nv_bfloat16* Bl = (__nv_bfloat16*)(smem + DT_BL);
    const int tid = threadIdx.x;
    const int d0 = blockIdx.x * 64;
    const int b0 = blockIdx.y * 32;

    // A: pure copy of g_TH/g_TL rows [32 b][160 r] -> ldm 160
#pragma unroll
    for (int v = tid; v < 640; v += 256) {
        const int m = v / 20, r8 = (v % 20) * 8;
        *(float4*)(Ah + m * 160 + r8) =
            *(const float4*)(g_TH + (b0 + m) * RR + r8);
        *(float4*)(Al + m * 160 + r8) =
            *(const float4*)(g_TL + (b0 + m) * RR + r8);
    }

    const int w = tid >> 5;
    const int mrow = w & 1;       // m = mrow*16
    const int nq = w >> 1;        // n = nq*16

    wmma::fragment<wmma::accumulator, 16, 16, 16, float> acc;
    wmma::fill_fragment(acc, 0.0f);

#pragma unroll
    for (int kc = 0; kc < 5; kc++) {      // chunks of K=32
        if (kc > 0) __syncthreads();      // prev-chunk mma readers done
        // B chunk: pure copy [32 k][64 d] bf16 -> ldm 72 (1 iter/thread)
        {
            const int k = tid >> 3, j8 = (tid & 7) * 8;
            *(float4*)(Bh + k * 72 + j8) =
                *(const float4*)(g_WDH + (size_t)(kc * 32 + k) * DD + d0 + j8);
            *(float4*)(Bl + k * 72 + j8) =
                *(const float4*)(g_WDL + (size_t)(kc * 32 + k) * DD + d0 + j8);
        }
        __syncthreads();
#pragma unroll
        for (int kk = 0; kk < 2; kk++) {
            wmma::fragment<wmma::matrix_a, 16, 16, 16, __nv_bfloat16, wmma::row_major> a_h, a_l;
            wmma::load_matrix_sync(a_h, Ah + mrow * 16 * 160 + kc * 32 + kk * 16, 160);
            wmma::load_matrix_sync(a_l, Al + mrow * 16 * 160 + kc * 32 + kk * 16, 160);
            wmma::fragment<wmma::matrix_b, 16, 16, 16, __nv_bfloat16, wmma::row_major> b_h, b_l;
            wmma::load_matrix_sync(b_h, Bh + kk * 16 * 72 + nq * 16, 72);
            wmma::load_matrix_sync(b_l, Bl + kk * 16 * 72 + nq * 16, 72);
            wmma::mma_sync(acc, a_h, b_h, acc);
            wmma::mma_sync(acc, a_h, b_l, acc);
            wmma::mma_sync(acc, a_l, b_h, acc);
        }
    }
    __syncthreads();   // all mma done before overwriting A region with staging

    // stage accumulators (fp32) into smem start, [32 m][64 n]
    float* st = (float*)smem;
    wmma::store_matrix_sync(st + (mrow * 16) * 64 + nq * 16, acc, 64,
                            wmma::mem_row_major);
    __syncthreads();

    // epilogue: dt = softplus(z + b_dt) -> g_DT (512 float4, 2/thread)
#pragma unroll
    for (int v = tid; v < 512; v += 256) {
        const int b = v >> 4, dq = (v & 15) << 2;
        float4 z4 = *(const float4*)&st[b * 64 + dq];
        float4 bd = *(const float4*)&bdt[d0 + dq];
        float4 dtv;
        float z0 = z4.x + bd.x, z1 = z4.y + bd.y, z2 = z4.z + bd.z, z3 = z4.w + bd.w;
        dtv.x = fmaxf(z0, 0.f) + log1pf(__expf(-fabsf(z0)));
        dtv.y = fmaxf(z1, 0.f) + log1pf(__expf(-fabsf(z1)));
        dtv.z = fmaxf(z2, 0.f) + log1pf(__expf(-fabsf(z2)));
        dtv.w = fmaxf(z3, 0.f) + log1pf(__expf(-fabsf(z3)));
        *(float4*)&g_DT[(size_t)(b0 + b) * DD + d0 + dq] = dtv;
    }
}

// ---------------------------------------------------------------------------
// Kernel 2b: h0 stream (R13/R14 version, unchanged).
// ---------------------------------------------------------------------------
__global__ __launch_bounds__(256) void mamba_scan_kernel(
    const float* __restrict__ x, const float* __restrict__ h0,
    const float* __restrict__ Alog, float* __restrict__ out)
{
    const int d0 = blockIdx.x * 128;
    const int b0 = blockIdx.y * 16;
    const int tid = threadIdx.x;
    const int lane = tid & 31;
    const int w = tid >> 5;

    __shared__ float A2s[128][16];
    __shared__ float dt_s[16][128];
    __shared__ float y_s[16][128];
    __shared__ float Cs[16][16];
    __shared__ float SBCs[16];

#pragma unroll
    for (int v = tid; v < 512; v += 256) {
        int di = v >> 2, n4 = (v & 3) << 2;
        float4 al = *(const float4*)&Alog[(size_t)(d0 + di) * NN + n4];
        float4 o;
        o.x = -__expf(al.x) * 1.44269504f;
        o.y = -__expf(al.y) * 1.44269504f;
        o.z = -__expf(al.z) * 1.44269504f;
        o.w = -__expf(al.w) * 1.44269504f;
        *(float4*)&A2s[di][n4] = o;
    }
#pragma unroll
    for (int v = tid; v < 512; v += 256) {
        int b = v >> 5, dq = (v & 31) << 2;
        *(float4*)&dt_s[b][dq] =
            *(const float4*)&g_DT[(size_t)(b0 + b) * DD + d0 + dq];
    }
    {
        int b = tid >> 4, n = tid & 15;
        Cs[b][n] = g_T[(b0 + b) * JJ + RR + NN + n];
    }
    if (tid < 16) {
        float s = 0.f;
#pragma unroll
        for (int n = 0; n < NN; n++)
            s += g_T[(b0 + tid) * JJ + RR + n] * g_T[(b0 + tid) * JJ + RR + NN + n];
        SBCs[tid] = s;
    }
    __syncthreads();

    {
        const int l4 = lane >> 2;
        const int n4 = (lane & 3) << 2;
        const int bA = w * 2, bB = w * 2 + 1;

        const float* hpA = &h0[((size_t)(b0 + bA) * DD + d0 + l4) * NN + n4];
        const float* hpB = hpA + (size_t)DD * NN;

        const float4 cA = *(const float4*)&Cs[bA][n4];
        const float4 cB = *(const float4*)&Cs[bB][n4];

        float4 hA0 = __ldcs((const float4*)hpA);
        float4 hB0 = __ldcs((const float4*)hpB);
        float4 hA1 = __ldcs((const float4*)(hpA + 128));
        float4 hB1 = __ldcs((const float4*)(hpB + 128));
        float4 hA2 = __ldcs((const float4*)(hpA + 256));
        float4 hB2 = __ldcs((const float4*)(hpB + 256));

#pragma unroll
        for (int dg = 0; dg < 16; dg++) {
            const int dloc = dg * 8 + l4;
            const float4 a2 = *(const float4*)&A2s[dloc][n4];
            const float dtA = dt_s[bA][dloc];
            const float dtB = dt_s[bB][dloc];

            float pA = ex2f(a2.x * dtA) * hA0.x * cA.x;
            pA = fmaf(ex2f(a2.y * dtA) * hA0.y, cA.y, pA);
            pA = fmaf(ex2f(a2.z * dtA) * hA0.z, cA.z, pA);
            pA = fmaf(ex2f(a2.w * dtA) * hA0.w, cA.w, pA);

            float pB = ex2f(a2.x * dtB) * hB0.x * cB.x;
            pB = fmaf(ex2f(a2.y * dtB) * hB0.y, cB.y, pB);
            pB = fmaf(ex2f(a2.z * dtB) * hB0.z, cB.z, pB);
            pB = fmaf(ex2f(a2.w * dtB) * hB0.w, cB.w, pB);

            hA0 = hA1; hB0 = hB1;
            hA1 = hA2; hB1 = hB2;
            if (dg < 13) {
                hA2 = __ldcs((const float4*)(hpA + (size_t)(dg + 3) * 128));
                hB2 = __ldcs((const float4*)(hpB + (size_t)(dg + 3) * 128));
            }

            pA += __shfl_xor_sync(0xffffffffu, pA, 1);
            pA += __shfl_xor_sync(0xffffffffu, pA, 2);
            pB += __shfl_xor_sync(0xffffffffu, pB, 1);
            pB += __shfl_xor_sync(0xffffffffu, pB, 2);
            if ((lane & 3) == 0) {
                y_s[bA][dloc] = pA;
                y_s[bB][dloc] = pB;
            }
        }
    }
    __syncthreads();

#pragma unroll
    for (int v = tid; v < 512; v += 256) {
        const int b = v >> 5, dq = (v & 31) << 2;
        const size_t g = (size_t)(b0 + b) * DD + d0 + dq;
        float4 xv = *(const float4*)&x[g];
        float4 dtv = *(const float4*)&dt_s[b][dq];
        float4 yv = *(const float4*)&y_s[b][dq];
        const float sbc = SBCs[b];
        float4 o;
        o.x = yv.x + fmaf(dtv.x * xv.x, sbc, xv.x);
        o.y = yv.y + fmaf(dtv.y * xv.y, sbc, xv.y);
        o.z = yv.z + fmaf(dtv.z * xv.z, sbc, xv.z);
        o.w = yv.w + fmaf(dtv.w * xv.w, sbc, xv.w);
        *(float4*)&out[g] = o;
    }
}

// ---------------------------------------------------------------------------
extern "C" void kernel_launch(void* const* d_in, const int* in_sizes, int n_in,
                              void* d_out, int out_size)
{
    const float* x    = (const float*)d_in[0];
    const float* h0   = (const float*)d_in[1];
    const float* Wx   = (const float*)d_in[2];
    const float* Wdt  = (const float*)d_in[3];
    const float* bdt  = (const float*)d_in[4];
    const float* Wbc  = (const float*)d_in[5];
    const float* Alog = (const float*)d_in[6];
    float* out = (float*)d_out;

    cudaFuncSetAttribute(mamba_proj_wmma,
                         cudaFuncAttributeMaxDynamicSharedMemorySize, PJ_SMEM);
    cudaFuncSetAttribute(mamba_dt_wmma,
                         cudaFuncAttributeMaxDynamicSharedMemorySize, DT_SMEM);
    mamba_prep<<<440, 256>>>(Wx, Wbc, Wdt, h0);
    mamba_proj_wmma<<<dim3(8, KSPLIT), 256, PJ_SMEM>>>(x);
    mamba_reduce_kernel<<<(BB * JJ) / 256, 256>>>();
    mamba_dt_wmma<<<dim3(DD / 64, BB / 32), 256, DT_SMEM>>>(bdt);
    mamba_scan_kernel<<<dim3(DD / 128, BB / 16), 256>>>(x, h0, Alog, out);
}

// round 16
// speedup vs baseline: 1.2934x; 1.2934x over previous
#include <cuda_runtime.h>
#include <cuda_bf16.h>
#include <mma.h>
#include <cstdint>

using namespace nvcuda;

#define BB 256
#define DD 5120
#define NN 16
#define RR 160
#define JJ 192          // RR + 32 (B/C projections)
#define KSPLIT 80
#define KCH 64          // DD / KSPLIT

// Scratch (device globals — no allocations allowed)
__device__ float g_P[KSPLIT * BB * JJ];   // split-K partials (15.7 MB)
__device__ float g_T[BB * JJ];            // reduced projections
__device__ float g_DT[BB * DD];           // dt (5.2 MB)

__device__ __forceinline__ float ex2f(float v) {
    float r;
    asm("ex2.approx.ftz.f32 %0, %1;" : "=f"(r) : "f"(v));
    return r;
}

typedef unsigned long long ull;

// Packed hi/lo bf16 split of a float4 (F2FP.BF16X2 path)
__device__ __forceinline__ void cvt_hilo4(float4 f, ull& hi, ull& lo) {
    union { ull u; __nv_bfloat162 h2[2]; } H, L;
    H.h2[0] = __float22bfloat162_rn(make_float2(f.x, f.y));
    H.h2[1] = __float22bfloat162_rn(make_float2(f.z, f.w));
    float2 g01 = __bfloat1622float2(H.h2[0]);
    float2 g23 = __bfloat1622float2(H.h2[1]);
    L.h2[0] = __float22bfloat162_rn(make_float2(f.x - g01.x, f.y - g01.y));
    L.h2[1] = __float22bfloat162_rn(make_float2(f.z - g23.x, f.w - g23.y));
    hi = H.u; lo = L.u;
}

// ---------------------------------------------------------------------------
// Kernel 1 (wmma, R14 version): split-K GEMM via HMMA, m-tile 32.
// P[ks] = x[:, ks*64 .. +64] @ [W_x_dt | W_BC], bf16 hi/lo 3-pass split.
// Grid (8, 80) = 640 CTAs, 256 threads, smem ~59 KB.
// ---------------------------------------------------------------------------
#define PJ_AH 0
#define PJ_AL 4608            // [32][72] bf16 = 4608 B each
#define PJ_BH 9216            // [64][200] bf16 = 25600 B each
#define PJ_BL 34816
#define PJ_SMEM 60416

__global__ __launch_bounds__(256) void mamba_proj_wmma(
    const float* __restrict__ x, const float* __restrict__ Wx,
    const float* __restrict__ Wbc, const float* __restrict__ h0)
{
    extern __shared__ __align__(128) char smem[];
    __nv_bfloat16* Ah = (__nv_bfloat16*)(smem + PJ_AH);
    __nv_bfloat16* Al = (__nv_bfloat16*)(smem + PJ_AL);
    __nv_bfloat16* Bh = (__nv_bfloat16*)(smem + PJ_BH);
    __nv_bfloat16* Bl = (__nv_bfloat16*)(smem + PJ_BL);
    const int tid = threadIdx.x;
    const int m0 = blockIdx.x * 32;
    const int ks = blockIdx.y;
    const int k0 = ks * KCH;

    // h0 L2 prefetch: 655360 lines over 640 CTAs = 1024/CTA, 4/thread
    {
        const int bid = blockIdx.x + blockIdx.y * 8;   // 0..639
        const size_t total = (size_t)BB * DD * NN;
        size_t base = (size_t)bid * 1024 * 32;
#pragma unroll
        for (int i = 0; i < 4; i++) {
            size_t off = base + (size_t)(tid + i * 256) * 32;
            if (off < total)
                asm volatile("prefetch.global.L2 [%0];" :: "l"(h0 + off) : "memory");
        }
    }

    // A: x[m0+m][k0+k] -> bf16 hi/lo, [32 m][72 ldm]
#pragma unroll
    for (int v = tid; v < 512; v += 256) {
        const int m = v >> 4, k4 = (v & 15) << 2;
        float4 xv = *(const float4*)&x[(size_t)(m0 + m) * DD + k0 + k4];
        ull hi, lo;
        cvt_hilo4(xv, hi, lo);
        *(ull*)(Ah + m * 72 + k4) = hi;
        *(ull*)(Al + m * 72 + k4) = lo;
    }
    // B: [64 k][200 ldm], cols 0..159 from Wx, 160..191 from Wbc
#pragma unroll
    for (int v = tid; v < 2560; v += 256) {
        const int k = v / 40, n4 = (v % 40) * 4;
        float4 wv = *(const float4*)&Wx[(size_t)(k0 + k) * RR + n4];
        ull hi, lo;
        cvt_hilo4(wv, hi, lo);
        *(ull*)(Bh + k * 200 + n4) = hi;
        *(ull*)(Bl + k * 200 + n4) = lo;
    }
#pragma unroll
    for (int v = tid; v < 512; v += 256) {
        const int k = v >> 3, n4 = 160 + (v & 7) * 4;
        float4 wv = *(const float4*)&Wbc[(size_t)(k0 + k) * 32 + (n4 - 160)];
        ull hi, lo;
        cvt_hilo4(wv, hi, lo);
        *(ull*)(Bh + k * 200 + n4) = hi;
        *(ull*)(Bl + k * 200 + n4) = lo;
    }
    __syncthreads();

    const int w = tid >> 5;
    const int mrow = w & 1;       // m = mrow*16
    const int nq = w >> 1;        // n base = nq*48

    wmma::fragment<wmma::accumulator, 16, 16, 16, float> acc[3];
#pragma unroll
    for (int j = 0; j < 3; j++) wmma::fill_fragment(acc[j], 0.0f);

#pragma unroll
    for (int kc = 0; kc < 4; kc++) {
        wmma::fragment<wmma::matrix_a, 16, 16, 16, __nv_bfloat16, wmma::row_major> a_h, a_l;
        wmma::load_matrix_sync(a_h, Ah + mrow * 16 * 72 + kc * 16, 72);
        wmma::load_matrix_sync(a_l, Al + mrow * 16 * 72 + kc * 16, 72);
#pragma unroll
        for (int j = 0; j < 3; j++) {
            const int n = nq * 48 + j * 16;
            wmma::fragment<wmma::matrix_b, 16, 16, 16, __nv_bfloat16, wmma::row_major> b_h, b_l;
            wmma::load_matrix_sync(b_h, Bh + kc * 16 * 200 + n, 200);
            wmma::load_matrix_sync(b_l, Bl + kc * 16 * 200 + n, 200);
            wmma::mma_sync(acc[j], a_h, b_h, acc[j]);
            wmma::mma_sync(acc[j], a_h, b_l, acc[j]);
            wmma::mma_sync(acc[j], a_l, b_h, acc[j]);
        }
    }

    float* dst = &g_P[(size_t)ks * (BB * JJ) + (size_t)(m0 + mrow * 16) * JJ + nq * 48];
#pragma unroll
    for (int j = 0; j < 3; j++)
        wmma::store_matrix_sync(dst + j * 16, acc[j], JJ, wmma::mem_row_major);
}

// ---------------------------------------------------------------------------
// Kernel 1r: reduce split-K partials. One thread per float, grid 192.
// ---------------------------------------------------------------------------
__global__ __launch_bounds__(256) void mamba_reduce_kernel()
{
    const int idx = blockIdx.x * 256 + threadIdx.x;
    float s = 0.f;
#pragma unroll
    for (int ks = 0; ks < KSPLIT; ks++) s += g_P[ks * (BB * JJ) + idx];
    g_T[idx] = s;
}

// ---------------------------------------------------------------------------
// Kernel 2a (wmma v2): dt GEMM. z = t @ W_dt + b_dt ; dt = softplus -> g_DT
// CTA 32(b) x 64(d). K=160 in TWO chunks of 80 (3 syncs total, was 10).
// A padded to ldm 168 (336B stride -> conflict-free LDSM; 160 was 4-way).
// smem 44.5 KB -> 5 CTAs/SM. Grid (80, 8) = 640 CTAs.
// Warp w: mrow = w&1 (m = mrow*16), nq = w>>1 (n = nq*16, 1 acc frag).
// ---------------------------------------------------------------------------
#define DT_LDA 168
#define DT_AH 0                  // [32][168] bf16 = 10752 B each
#define DT_AL 10752
#define DT_BH 21504              // [80][72] bf16 = 11520 B each
#define DT_BL 33024
#define DT_SMEM 44544            // staging [32][64] f32 = 8192 reuses A region

__global__ __launch_bounds__(256) void mamba_dt_wmma(
    const float* __restrict__ Wdt, const float* __restrict__ bdt)
{
    extern __shared__ __align__(128) char smem[];
    __nv_bfloat16* Ah = (__nv_bfloat16*)(smem + DT_AH);
    __nv_bfloat16* Al = (__nv_bfloat16*)(smem + DT_AL);
    __nv_bfloat16* Bh = (__nv_bfloat16*)(smem + DT_BH);
    __nv_bfloat16* Bl = (__nv_bfloat16*)(smem + DT_BL);
    const int tid = threadIdx.x;
    const int d0 = blockIdx.x * 64;
    const int b0 = blockIdx.y * 32;

    // A: g_T[b0+m][r] (32 x 160) -> bf16 hi/lo, ldm 168 (1280 float4)
#pragma unroll
    for (int v = tid; v < 1280; v += 256) {
        const int m = v / 40, r4 = (v % 40) * 4;
        float4 t4 = *(const float4*)&g_T[(b0 + m) * JJ + r4];
        ull hi, lo;
        cvt_hilo4(t4, hi, lo);
        *(ull*)(Ah + m * DT_LDA + r4) = hi;
        *(ull*)(Al + m * DT_LDA + r4) = lo;
    }

    const int w = tid >> 5;
    const int mrow = w & 1;       // m = mrow*16
    const int nq = w >> 1;        // n = nq*16

    wmma::fragment<wmma::accumulator, 16, 16, 16, float> acc;
    wmma::fill_fragment(acc, 0.0f);

#pragma unroll
    for (int kc = 0; kc < 2; kc++) {      // chunks of K=80
        if (kc > 0) __syncthreads();      // prev-chunk mma readers done
        // B chunk: Wdt[(kc*80 + k)*DD + d0 + n], 80 x 64 -> hi/lo, ldm 72
        // 1280 float4 over 256 threads = 5 iters
#pragma unroll
        for (int v = tid; v < 1280; v += 256) {
            const int k = v >> 4, n4 = (v & 15) << 2;
            float4 wv = *(const float4*)&Wdt[(size_t)(kc * 80 + k) * DD + d0 + n4];
            ull hi, lo;
            cvt_hilo4(wv, hi, lo);
            *(ull*)(Bh + k * 72 + n4) = hi;
            *(ull*)(Bl + k * 72 + n4) = lo;
        }
        __syncthreads();
#pragma unroll
        for (int kk = 0; kk < 5; kk++) {
            wmma::fragment<wmma::matrix_a, 16, 16, 16, __nv_bfloat16, wmma::row_major> a_h, a_l;
            wmma::load_matrix_sync(a_h, Ah + mrow * 16 * DT_LDA + kc * 80 + kk * 16, DT_LDA);
            wmma::load_matrix_sync(a_l, Al + mrow * 16 * DT_LDA + kc * 80 + kk * 16, DT_LDA);
            wmma::fragment<wmma::matrix_b, 16, 16, 16, __nv_bfloat16, wmma::row_major> b_h, b_l;
            wmma::load_matrix_sync(b_h, Bh + kk * 16 * 72 + nq * 16, 72);
            wmma::load_matrix_sync(b_l, Bl + kk * 16 * 72 + nq * 16, 72);
            wmma::mma_sync(acc, a_h, b_h, acc);
            wmma::mma_sync(acc, a_h, b_l, acc);
            wmma::mma_sync(acc, a_l, b_h, acc);
        }
    }
    __syncthreads();   // all mma done before overwriting A region with staging

    // stage accumulators (fp32) into smem start, [32 m][64 n]
    float* st = (float*)smem;
    wmma::store_matrix_sync(st + (mrow * 16) * 64 + nq * 16, acc, 64,
                            wmma::mem_row_major);
    __syncthreads();

    // epilogue: dt = softplus(z + b_dt) -> g_DT (512 float4, 2/thread)
#pragma unroll
    for (int v = tid; v < 512; v += 256) {
        const int b = v >> 4, dq = (v & 15) << 2;
        float4 z4 = *(const float4*)&st[b * 64 + dq];
        float4 bd = *(const float4*)&bdt[d0 + dq];
        float4 dtv;
        float z0 = z4.x + bd.x, z1 = z4.y + bd.y, z2 = z4.z + bd.z, z3 = z4.w + bd.w;
        dtv.x = fmaxf(z0, 0.f) + log1pf(__expf(-fabsf(z0)));
        dtv.y = fmaxf(z1, 0.f) + log1pf(__expf(-fabsf(z1)));
        dtv.z = fmaxf(z2, 0.f) + log1pf(__expf(-fabsf(z2)));
        dtv.w = fmaxf(z3, 0.f) + log1pf(__expf(-fabsf(z3)));
        *(float4*)&g_DT[(size_t)(b0 + b) * DD + d0 + dq] = dtv;
    }
}

// ---------------------------------------------------------------------------
// Kernel 2b: h0 stream (R13/R14 version, unchanged).
// ---------------------------------------------------------------------------
__global__ __launch_bounds__(256) void mamba_scan_kernel(
    const float* __restrict__ x, const float* __restrict__ h0,
    const float* __restrict__ Alog, float* __restrict__ out)
{
    const int d0 = blockIdx.x * 128;
    const int b0 = blockIdx.y * 16;
    const int tid = threadIdx.x;
    const int lane = tid & 31;
    const int w = tid >> 5;

    __shared__ float A2s[128][16];
    __shared__ float dt_s[16][128];
    __shared__ float y_s[16][128];
    __shared__ float Cs[16][16];
    __shared__ float SBCs[16];

#pragma unroll
    for (int v = tid; v < 512; v += 256) {
        int di = v >> 2, n4 = (v & 3) << 2;
        float4 al = *(const float4*)&Alog[(size_t)(d0 + di) * NN + n4];
        float4 o;
        o.x = -__expf(al.x) * 1.44269504f;
        o.y = -__expf(al.y) * 1.44269504f;
        o.z = -__expf(al.z) * 1.44269504f;
        o.w = -__expf(al.w) * 1.44269504f;
        *(float4*)&A2s[di][n4] = o;
    }
#pragma unroll
    for (int v = tid; v < 512; v += 256) {
        int b = v >> 5, dq = (v & 31) << 2;
        *(float4*)&dt_s[b][dq] =
            *(const float4*)&g_DT[(size_t)(b0 + b) * DD + d0 + dq];
    }
    {
        int b = tid >> 4, n = tid & 15;
        Cs[b][n] = g_T[(b0 + b) * JJ + RR + NN + n];
    }
    if (tid < 16) {
        float s = 0.f;
#pragma unroll
        for (int n = 0; n < NN; n++)
            s += g_T[(b0 + tid) * JJ + RR + n] * g_T[(b0 + tid) * JJ + RR + NN + n];
        SBCs[tid] = s;
    }
    __syncthreads();

    {
        const int l4 = lane >> 2;
        const int n4 = (lane & 3) << 2;
        const int bA = w * 2, bB = w * 2 + 1;

        const float* hpA = &h0[((size_t)(b0 + bA) * DD + d0 + l4) * NN + n4];
        const float* hpB = hpA + (size_t)DD * NN;

        const float4 cA = *(const float4*)&Cs[bA][n4];
        const float4 cB = *(const float4*)&Cs[bB][n4];

        float4 hA0 = __ldcs((const float4*)hpA);
        float4 hB0 = __ldcs((const float4*)hpB);
        float4 hA1 = __ldcs((const float4*)(hpA + 128));
        float4 hB1 = __ldcs((const float4*)(hpB + 128));
        float4 hA2 = __ldcs((const float4*)(hpA + 256));
        float4 hB2 = __ldcs((const float4*)(hpB + 256));

#pragma unroll
        for (int dg = 0; dg < 16; dg++) {
            const int dloc = dg * 8 + l4;
            const float4 a2 = *(const float4*)&A2s[dloc][n4];
            const float dtA = dt_s[bA][dloc];
            const float dtB = dt_s[bB][dloc];

            float pA = ex2f(a2.x * dtA) * hA0.x * cA.x;
            pA = fmaf(ex2f(a2.y * dtA) * hA0.y, cA.y, pA);
            pA = fmaf(ex2f(a2.z * dtA) * hA0.z, cA.z, pA);
            pA = fmaf(ex2f(a2.w * dtA) * hA0.w, cA.w, pA);

            float pB = ex2f(a2.x * dtB) * hB0.x * cB.x;
            pB = fmaf(ex2f(a2.y * dtB) * hB0.y, cB.y, pB);
            pB = fmaf(ex2f(a2.z * dtB) * hB0.z, cB.z, pB);
            pB = fmaf(ex2f(a2.w * dtB) * hB0.w, cB.w, pB);

            hA0 = hA1; hB0 = hB1;
            hA1 = hA2; hB1 = hB2;
            if (dg < 13) {
                hA2 = __ldcs((const float4*)(hpA + (size_t)(dg + 3) * 128));
                hB2 = __ldcs((const float4*)(hpB + (size_t)(dg + 3) * 128));
            }

            pA += __shfl_xor_sync(0xffffffffu, pA, 1);
            pA += __shfl_xor_sync(0xffffffffu, pA, 2);
            pB += __shfl_xor_sync(0xffffffffu, pB, 1);
            pB += __shfl_xor_sync(0xffffffffu, pB, 2);
            if ((lane & 3) == 0) {
                y_s[bA][dloc] = pA;
                y_s[bB][dloc] = pB;
            }
        }
    }
    __syncthreads();

#pragma unroll
    for (int v = tid; v < 512; v += 256) {
        const int b = v >> 5, dq = (v & 31) << 2;
        const size_t g = (size_t)(b0 + b) * DD + d0 + dq;
        float4 xv = *(const float4*)&x[g];
        float4 dtv = *(const float4*)&dt_s[b][dq];
        float4 yv = *(const float4*)&y_s[b][dq];
        const float sbc = SBCs[b];
        float4 o;
        o.x = yv.x + fmaf(dtv.x * xv.x, sbc, xv.x);
        o.y = yv.y + fmaf(dtv.y * xv.y, sbc, xv.y);
        o.z = yv.z + fmaf(dtv.z * xv.z, sbc, xv.z);
        o.w = yv.w + fmaf(dtv.w * xv.w, sbc, xv.w);
        *(float4*)&out[g] = o;
    }
}

// ---------------------------------------------------------------------------
extern "C" void kernel_launch(void* const* d_in, const int* in_sizes, int n_in,
                              void* d_out, int out_size)
{
    const float* x    = (const float*)d_in[0];
    const float* h0   = (const float*)d_in[1];
    const float* Wx   = (const float*)d_in[2];
    const float* Wdt  = (const float*)d_in[3];
    const float* bdt  = (const float*)d_in[4];
    const float* Wbc  = (const float*)d_in[5];
    const float* Alog = (const float*)d_in[6];
    float* out = (float*)d_out;

    cudaFuncSetAttribute(mamba_proj_wmma,
                         cudaFuncAttributeMaxDynamicSharedMemorySize, PJ_SMEM);
    cudaFuncSetAttribute(mamba_dt_wmma,
                         cudaFuncAttributeMaxDynamicSharedMemorySize, DT_SMEM);
    mamba_proj_wmma<<<dim3(8, KSPLIT), 256, PJ_SMEM>>>(x, Wx, Wbc, h0);
    mamba_reduce_kernel<<<(BB * JJ) / 256, 256>>>();
    mamba_dt_wmma<<<dim3(DD / 64, BB / 32), 256, DT_SMEM>>>(Wdt, bdt);
    mamba_scan_kernel<<<dim3(DD / 128, BB / 16), 256>>>(x, h0, Alog, out);
}